// round 15
// baseline (speedup 1.0000x reference)
#include <cuda_runtime.h>
#include <cuda_bf16.h>
#include <cuda_fp16.h>
#include <math.h>
#include <stdint.h>

// ---------------------------------------------------------------------------
// Problem constants (R10-best config: QKV4 / O4 / FF2 8, ff1 fused relu)
// ---------------------------------------------------------------------------
#define TI_   128
#define NB_   8
#define TO_   32
#define TS_   33
#define D_    512
#define H_    8
#define HD_   64
#define FF_   2048
#define V_    2000
#define VP_   2048
#define L_    6
#define TOK_  (TS_ * NB_)          // 264
#define MJ_   (NB_ * TI_ * TS_)    // 33792
#define FF2_SPLIT 8
#define QKV_SPLIT 4
#define O_SPLIT   4

// ---------------------------------------------------------------------------
// Scratch
// ---------------------------------------------------------------------------
__device__ float g_x[TOK_ * D_];
__device__ float g_qkv[QKV_SPLIT * TOK_ * 3 * D_];
__device__ float g_tmp[FF2_SPLIT * TOK_ * D_];
__device__ float g_encp[TI_ * NB_ * D_];

__device__ __nv_bfloat16 g_xh[TOK_ * D_],  g_xl[TOK_ * D_];
__device__ __nv_bfloat16 g_ath[TOK_ * D_], g_atl[TOK_ * D_];
__device__ __nv_bfloat16 g_fh[TOK_ * FF_], g_fl[TOK_ * FF_];

__device__ __nv_bfloat16 g_qkvwh[(size_t)L_ * 3 * D_ * D_], g_qkvwl[(size_t)L_ * 3 * D_ * D_];
__device__ __nv_bfloat16 g_owh[(size_t)L_ * D_ * D_],       g_owl[(size_t)L_ * D_ * D_];
__device__ __nv_bfloat16 g_f1h[(size_t)L_ * FF_ * D_],      g_f1l[(size_t)L_ * FF_ * D_];
__device__ __nv_bfloat16 g_f2h[(size_t)L_ * D_ * FF_],      g_f2l[(size_t)L_ * D_ * FF_];

// fp16 operands: enc projection + joiner
__device__ __half g_exf[TI_ * NB_ * D_];   // enc_out fp16
__device__ __half g_ewf[D_ * D_];          // enc_w fp16
__device__ __half g_Aj[(size_t)MJ_ * D_];
__device__ __half g_Wj[(size_t)VP_ * D_];

// ---------------------------------------------------------------------------
// PTX helpers
// ---------------------------------------------------------------------------
__device__ __forceinline__ uint32_t smem_to_u32(const void* smem_ptr) {
    uint32_t addr;
    asm("{ .reg .u64 tmp; cvta.to.shared.u64 tmp, %1; cvt.u32.u64 %0, tmp; }"
        : "=r"(addr) : "l"(smem_ptr));
    return addr;
}
__device__ __forceinline__ uint32_t sw_off(uint32_t bo) {
    return bo ^ ((bo >> 3) & 0x70);
}
__device__ __forceinline__ void cp_async16(uint32_t saddr, const void* gptr, int valid) {
    asm volatile("cp.async.cg.shared.global [%0], [%1], 16, %2;"
        :: "r"(saddr), "l"(gptr), "r"(valid ? 16 : 0));
}
__device__ __forceinline__ void cp_async_commit() {
    asm volatile("cp.async.commit_group;");
}
template <int N>
__device__ __forceinline__ void cp_async_wait() {
    asm volatile("cp.async.wait_group %0;" :: "n"(N) : "memory");
}
__device__ __forceinline__ void stg_cs_f2(float* p, float a, float b) {
    asm volatile("st.global.cs.v2.f32 [%0], {%1,%2};" :: "l"(p), "f"(a), "f"(b) : "memory");
}

// ---------------------------------------------------------------------------
// mma.sync helpers
// ---------------------------------------------------------------------------
__device__ __forceinline__ void ldmatrix_x4(uint32_t* r, uint32_t addr) {
    asm volatile("ldmatrix.sync.aligned.m8n8.x4.shared.b16 {%0,%1,%2,%3}, [%4];"
        : "=r"(r[0]), "=r"(r[1]), "=r"(r[2]), "=r"(r[3]) : "r"(addr));
}
__device__ __forceinline__ void mma16816(float* d, const uint32_t* a,
                                         uint32_t b0, uint32_t b1) {
    asm volatile(
        "mma.sync.aligned.m16n8k16.row.col.f32.bf16.bf16.f32 "
        "{%0,%1,%2,%3}, {%4,%5,%6,%7}, {%8,%9}, {%0,%1,%2,%3};"
        : "+f"(d[0]), "+f"(d[1]), "+f"(d[2]), "+f"(d[3])
        : "r"(a[0]), "r"(a[1]), "r"(a[2]), "r"(a[3]), "r"(b0), "r"(b1));
}
__device__ __forceinline__ void mma16816_f16(float* d, const uint32_t* a,
                                             uint32_t b0, uint32_t b1) {
    asm volatile(
        "mma.sync.aligned.m16n8k16.row.col.f32.f16.f16.f32 "
        "{%0,%1,%2,%3}, {%4,%5,%6,%7}, {%8,%9}, {%0,%1,%2,%3};"
        : "+f"(d[0]), "+f"(d[1]), "+f"(d[2]), "+f"(d[3])
        : "r"(a[0]), "r"(a[1]), "r"(a[2]), "r"(a[3]), "r"(b0), "r"(b1));
}

__device__ __forceinline__ void split_hl(float v, __nv_bfloat16& h, __nv_bfloat16& l) {
    h = __float2bfloat16(v);
    l = __float2bfloat16(v - __bfloat162float(h));
}

// ---------------------------------------------------------------------------
// Fused weight split (4 bf16 hi/lo jobs)
// ---------------------------------------------------------------------------
#define NSPLITJOBS 4
struct SplitJobs {
    const float* src[NSPLITJOBS];
    __nv_bfloat16* h[NSPLITJOBS];
    __nv_bfloat16* l[NSPLITJOBS];
    int end[NSPLITJOBS];
};

__global__ void split_all_kernel(SplitJobs jobs, int total) {
    int i = blockIdx.x * blockDim.x + threadIdx.x;
    if (i >= total) return;
    int j = 0;
#pragma unroll
    for (int k = 0; k < NSPLITJOBS - 1; k++) j += (i >= jobs.end[k]);
    int base = (j == 0) ? 0 : jobs.end[j - 1];
    int li = i - base;
    float4 w = ((const float4*)jobs.src[j])[li];
    __nv_bfloat16 h0, h1, h2, h3, l0, l1, l2, l3;
    split_hl(w.x, h0, l0); split_hl(w.y, h1, l1);
    split_hl(w.z, h2, l2); split_hl(w.w, h3, l3);
    ((__nv_bfloat162*)jobs.h[j])[2 * li]     = __nv_bfloat162(h0, h1);
    ((__nv_bfloat162*)jobs.h[j])[2 * li + 1] = __nv_bfloat162(h2, h3);
    ((__nv_bfloat162*)jobs.l[j])[2 * li]     = __nv_bfloat162(l0, l1);
    ((__nv_bfloat162*)jobs.l[j])[2 * li + 1] = __nv_bfloat162(l2, l3);
}

// enc_out + enc_w -> fp16
__global__ void enc_f16_kernel(const float* __restrict__ enc_out,
                               const float* __restrict__ enc_w,
                               __half* __restrict__ exf,
                               __half* __restrict__ ewf) {
    const int n0 = TI_ * NB_ * D_ / 4;
    const int n1 = D_ * D_ / 4;
    int i = blockIdx.x * blockDim.x + threadIdx.x;
    if (i < n0) {
        float4 w = ((const float4*)enc_out)[i];
        ((__half2*)exf)[2 * i]     = __half2(__float2half(w.x), __float2half(w.y));
        ((__half2*)exf)[2 * i + 1] = __half2(__float2half(w.z), __float2half(w.w));
    } else if (i < n0 + n1) {
        int li = i - n0;
        float4 w = ((const float4*)enc_w)[li];
        ((__half2*)ewf)[2 * li]     = __half2(__float2half(w.x), __float2half(w.y));
        ((__half2*)ewf)[2 * li + 1] = __half2(__float2half(w.z), __float2half(w.w));
    }
}

// out_w -> single fp16, padded to VP_ rows
__global__ void w_split_kernel(const float* __restrict__ W,
                               __half* __restrict__ Wj) {
    int r = blockIdx.x;
    int tid = threadIdx.x;
    size_t base = (size_t)r * D_ + tid * 4;
    if (r < V_) {
        const float4 w = ((const float4*)(W + (size_t)r * D_))[tid];
        ((__half2*)(Wj + base))[0] = __half2(__float2half(w.x), __float2half(w.y));
        ((__half2*)(Wj + base))[1] = __half2(__float2half(w.z), __float2half(w.w));
    } else {
        __half2 z = __half2(__float2half(0.f), __float2half(0.f));
        ((__half2*)(Wj + base))[0] = z;
        ((__half2*)(Wj + base))[1] = z;
    }
}

// ---------------------------------------------------------------------------
// Embedding + positions
// ---------------------------------------------------------------------------
__global__ void embed_kernel(const float* __restrict__ embed,
                             const int* __restrict__ tgt_pad,
                             const int* __restrict__ sos,
                             float* __restrict__ x,
                             __nv_bfloat16* __restrict__ xh,
                             __nv_bfloat16* __restrict__ xl) {
    int r = blockIdx.x;
    int t = r >> 3, n = r & 7;
    int tok = (t == 0) ? sos[0] : tgt_pad[n * TO_ + (t - 1)];
    const float* e = embed + (size_t)tok * D_;
    const float sc = sqrtf(512.0f);
    int tid = threadIdx.x;
#pragma unroll
    for (int i = 0; i < 2; i++) {
        int d = tid * 4 + i * 2;
        float ddiv = expf((float)d * (-9.210340371976184f / 512.0f));
        float ang = (float)t * ddiv;
        float sv, cv;
        sincosf(ang, &sv, &cv);
        size_t idx = (size_t)r * D_ + d;
        float v0 = e[d] * sc + sv;
        float v1 = e[d + 1] * sc + cv;
        x[idx] = v0; x[idx + 1] = v1;
        __nv_bfloat16 h0, l0, h1, l1;
        split_hl(v0, h0, l0); split_hl(v1, h1, l1);
        xh[idx] = h0; xh[idx + 1] = h1;
        xl[idx] = l0; xl[idx + 1] = l1;
    }
}

// ---------------------------------------------------------------------------
// Tile loaders
// ---------------------------------------------------------------------------
__device__ __forceinline__ void tc_load_half_async(const __nv_bfloat16* __restrict__ src,
                                                   int row0, int maxrow, int kelem,
                                                   int kstride, uint32_t sm, int tid, int p) {
#pragma unroll
    for (int q = 0; q < 2; q++) {
        int idx = q * 256 + tid;
        int row = idx >> 2, seg = idx & 3;
        int gr = row0 + row;
        uint32_t bo = (uint32_t)(row * 128 + p * 64 + seg * 16);
        cp_async16(sm + sw_off(bo),
                   src + (size_t)gr * kstride + kelem + seg * 8,
                   gr < maxrow);
    }
}

// layer-chain GEMM smem layout (bf16 3-term)
#define JT_BUF      16384
#define JT_SM_AH    1024
#define JT_SM_AL    (JT_SM_AH + JT_BUF)
#define JT_SM_WH    (JT_SM_AL + JT_BUF)
#define JT_SM_WL    (JT_SM_WH + JT_BUF)
#define JT_SMEM     (JT_SM_WL + JT_BUF)      // 66560

// fp16 GEMM smem layout (A, W)
#define JJ_SM_A     1024
#define JJ_SM_W     (JJ_SM_A + JT_BUF)
#define JJ_SMEM     (JJ_SM_W + JT_BUF)       // 33792

__device__ __forceinline__ void load_half4(const __nv_bfloat16* Ah, const __nv_bfloat16* Al,
                                           const __nv_bfloat16* Wh, const __nv_bfloat16* Wl,
                                           int m0, int M, int n0, int N,
                                           int kelem, int kstride,
                                           uint32_t sbase, int tid, int p) {
    tc_load_half_async(Ah, m0, M, kelem, kstride, sbase + JT_SM_AH, tid, p);
    tc_load_half_async(Al, m0, M, kelem, kstride, sbase + JT_SM_AL, tid, p);
    tc_load_half_async(Wh, n0, N, kelem, kstride, sbase + JT_SM_WH, tid, p);
    tc_load_half_async(Wl, n0, N, kelem, kstride, sbase + JT_SM_WL, tid, p);
}
__device__ __forceinline__ void load_half2_f16(const __half* A, const __half* W,
                                               int m0, int M, int n0, int N,
                                               int kelem, uint32_t sbase, int tid, int p) {
    tc_load_half_async((const __nv_bfloat16*)A, m0, M, kelem, D_, sbase + JJ_SM_A, tid, p);
    tc_load_half_async((const __nv_bfloat16*)W, n0, N, kelem, D_, sbase + JJ_SM_W, tid, p);
}

// ---------------------------------------------------------------------------
// Chain mainloop with A-fragment hoist
// ---------------------------------------------------------------------------
__device__ __forceinline__ void mma_mainloop_half(uint32_t sbase, int wr, int wc,
                                                  int lane, float acc[16][4], int p) {
    const int boffs[3] = {JT_SM_WH, JT_SM_WL, JT_SM_WH};
    const int bt = lane >> 3, br_ = lane & 7;
#pragma unroll
    for (int si = 0; si < 2; si++) {
        const int s = 2 * p + si;
        uint32_t AH[2][4], AL[2][4];
#pragma unroll
        for (int mi = 0; mi < 2; mi++) {
            uint32_t bo = (uint32_t)((wr * 32 + mi * 16 + (lane & 15)) * 128
                                     + s * 32 + (lane >> 4) * 16);
            ldmatrix_x4(AH[mi], sbase + JT_SM_AH + sw_off(bo));
            ldmatrix_x4(AL[mi], sbase + JT_SM_AL + sw_off(bo));
        }
#pragma unroll
        for (int tm = 0; tm < 3; tm++) {
            const uint32_t (*af)[4] = (tm == 2) ? AL : AH;
#pragma unroll
            for (int g = 0; g < 4; g++) {
                uint32_t bo = (uint32_t)((wc * 64 + g * 16 + (bt >> 1) * 8 + br_) * 128
                                         + s * 32 + (bt & 1) * 16);
                uint32_t bfr[4];
                ldmatrix_x4(bfr, sbase + boffs[tm] + sw_off(bo));
                mma16816(acc[2 * g],     af[0], bfr[0], bfr[1]);
                mma16816(acc[8 + 2 * g], af[1], bfr[0], bfr[1]);
                mma16816(acc[2 * g + 1],     af[0], bfr[2], bfr[3]);
                mma16816(acc[8 + 2 * g + 1], af[1], bfr[2], bfr[3]);
            }
        }
    }
}
// fp16 single-term mainloop over one 32-element half
__device__ __forceinline__ void mma_mainloop_half_f16(uint32_t sbase, int wr, int wc,
                                                      int lane, float acc[16][4], int p) {
    const int bt = lane >> 3, br_ = lane & 7;
#pragma unroll
    for (int si = 0; si < 2; si++) {
        const int s = 2 * p + si;
        uint32_t afrag[2][4];
#pragma unroll
        for (int mi = 0; mi < 2; mi++) {
            uint32_t bo = (uint32_t)((wr * 32 + mi * 16 + (lane & 15)) * 128
                                     + s * 32 + (lane >> 4) * 16);
            ldmatrix_x4(afrag[mi], sbase + JJ_SM_A + sw_off(bo));
        }
#pragma unroll
        for (int g = 0; g < 4; g++) {
            uint32_t bo = (uint32_t)((wc * 64 + g * 16 + (bt >> 1) * 8 + br_) * 128
                                     + s * 32 + (bt & 1) * 16);
            uint32_t bfr[4];
            ldmatrix_x4(bfr, sbase + JJ_SM_W + sw_off(bo));
            mma16816_f16(acc[2 * g],     afrag[0], bfr[0], bfr[1]);
            mma16816_f16(acc[8 + 2 * g], afrag[1], bfr[0], bfr[1]);
            mma16816_f16(acc[2 * g + 1],     afrag[0], bfr[2], bfr[3]);
            mma16816_f16(acc[8 + 2 * g + 1], afrag[1], bfr[2], bfr[3]);
        }
    }
}

// ---------------------------------------------------------------------------
// Layer-chain tensor GEMM (3-term bf16 hi/lo), half-buffer pipelined
// ---------------------------------------------------------------------------
__global__ void __launch_bounds__(256) gemm_tc(
    const __nv_bfloat16* __restrict__ Ah, const __nv_bfloat16* __restrict__ Al,
    const __nv_bfloat16* __restrict__ Wh, const __nv_bfloat16* __restrict__ Wl,
    const float* __restrict__ bias,
    float* __restrict__ C,
    __nv_bfloat16* __restrict__ Ch, __nv_bfloat16* __restrict__ Cl,
    int M, int N, int kstride, int chunks, int relu) {
    extern __shared__ char smem[];
    const uint32_t sbase = smem_to_u32(smem);
    const int tid = threadIdx.x;
    const int n0 = blockIdx.x * 128;
    const int m0 = blockIdx.y * 128;
    const int z  = blockIdx.z;
    const int koff0 = z * chunks * 64;
    if (C) C += (size_t)z * M * N;

    const int w = tid >> 5, lane = tid & 31;
    const int wr = w >> 1, wc = w & 1;

    float acc[16][4];
#pragma unroll
    for (int i = 0; i < 16; i++)
#pragma unroll
        for (int j = 0; j < 4; j++) acc[i][j] = 0.f;

    const int nhalf = chunks * 2;
    load_half4(Ah, Al, Wh, Wl, m0, M, n0, N, koff0, kstride, sbase, tid, 0);
    cp_async_commit();
    for (int c = 0; c < nhalf; c++) {
        if (c + 1 < nhalf) {
            load_half4(Ah, Al, Wh, Wl, m0, M, n0, N,
                       koff0 + (c + 1) * 32, kstride, sbase, tid, (c + 1) & 1);
            cp_async_commit();
            cp_async_wait<1>();
        } else {
            cp_async_wait<0>();
        }
        __syncthreads();
        mma_mainloop_half(sbase, wr, wc, lane, acc, c & 1);
        __syncthreads();
    }

    const bool addb = (bias != nullptr) && (z == 0);
#pragma unroll
    for (int mi = 0; mi < 2; mi++) {
#pragma unroll
        for (int nt = 0; nt < 8; nt++) {
            int m = m0 + wr * 32 + mi * 16 + (lane >> 2);
            int ncol = n0 + wc * 64 + nt * 8 + 2 * (lane & 3);
            float b0v = addb ? bias[ncol] : 0.f;
            float b1v = addb ? bias[ncol + 1] : 0.f;
            float v0 = acc[mi * 8 + nt][0] + b0v;
            float v1 = acc[mi * 8 + nt][1] + b1v;
            float v2 = acc[mi * 8 + nt][2] + b0v;
            float v3 = acc[mi * 8 + nt][3] + b1v;
            if (relu) {
                v0 = fmaxf(v0, 0.f); v1 = fmaxf(v1, 0.f);
                v2 = fmaxf(v2, 0.f); v3 = fmaxf(v3, 0.f);
            }
            if (m < M) {
                size_t o = (size_t)m * N + ncol;
                if (C) *(float2*)(C + o) = make_float2(v0, v1);
                if (Ch) {
                    __nv_bfloat16 h0, h1, l0, l1;
                    split_hl(v0, h0, l0); split_hl(v1, h1, l1);
                    *(__nv_bfloat162*)(Ch + o) = __nv_bfloat162(h0, h1);
                    *(__nv_bfloat162*)(Cl + o) = __nv_bfloat162(l0, l1);
                }
            }
            if (m + 8 < M) {
                size_t o = (size_t)(m + 8) * N + ncol;
                if (C) *(float2*)(C + o) = make_float2(v2, v3);
                if (Ch) {
                    __nv_bfloat16 h0, h1, l0, l1;
                    split_hl(v2, h0, l0); split_hl(v3, h1, l1);
                    *(__nv_bfloat162*)(Ch + o) = __nv_bfloat162(h0, h1);
                    *(__nv_bfloat162*)(Cl + o) = __nv_bfloat162(l0, l1);
                }
            }
        }
    }
}

// ---------------------------------------------------------------------------
// fp16 single-term GEMM (enc projection): C[M,N] = A @ W^T + bias, fp32 out
// M, N multiples of 128. K = 512.
// ---------------------------------------------------------------------------
__global__ void __launch_bounds__(256) gemm_f16(
    const __half* __restrict__ A,
    const __half* __restrict__ W,
    const float* __restrict__ bias,
    float* __restrict__ C,
    int M, int N) {
    extern __shared__ char smem[];
    const uint32_t sbase = smem_to_u32(smem);
    const int tid = threadIdx.x;
    const int n0 = blockIdx.x * 128;
    const int m0 = blockIdx.y * 128;

    const int w = tid >> 5, lane = tid & 31;
    const int wr = w >> 1, wc = w & 1;

    float acc[16][4];
#pragma unroll
    for (int i = 0; i < 16; i++)
#pragma unroll
        for (int j = 0; j < 4; j++) acc[i][j] = 0.f;

    const int nhalf = 16;   // K=512 / 32
    load_half2_f16(A, W, m0, M, n0, N, 0, sbase, tid, 0);
    cp_async_commit();
    for (int c = 0; c < nhalf; c++) {
        if (c + 1 < nhalf) {
            load_half2_f16(A, W, m0, M, n0, N, (c + 1) * 32, sbase, tid, (c + 1) & 1);
            cp_async_commit();
            cp_async_wait<1>();
        } else {
            cp_async_wait<0>();
        }
        __syncthreads();
        mma_mainloop_half_f16(sbase, wr, wc, lane, acc, c & 1);
        __syncthreads();
    }

#pragma unroll
    for (int mi = 0; mi < 2; mi++) {
#pragma unroll
        for (int nt = 0; nt < 8; nt++) {
            int m = m0 + wr * 32 + mi * 16 + (lane >> 2);
            int ncol = n0 + wc * 64 + nt * 8 + 2 * (lane & 3);
            float b0v = bias[ncol], b1v = bias[ncol + 1];
            *(float2*)(C + (size_t)m * N + ncol) =
                make_float2(acc[mi * 8 + nt][0] + b0v, acc[mi * 8 + nt][1] + b1v);
            *(float2*)(C + (size_t)(m + 8) * N + ncol) =
                make_float2(acc[mi * 8 + nt][2] + b0v, acc[mi * 8 + nt][3] + b1v);
        }
    }
}

// ---------------------------------------------------------------------------
// Attention: 256 threads, warp-parallel softmax, vectorized dots
// ---------------------------------------------------------------------------
__global__ void __launch_bounds__(256) attention_kernel(
    const float* __restrict__ qkv,
    const int* __restrict__ tgt_len,
    __nv_bfloat16* __restrict__ oh,
    __nv_bfloat16* __restrict__ ol) {
    int n = blockIdx.x >> 3, h = blockIdx.x & 7;
    __shared__ float qs[TS_][HD_];
    __shared__ float ks[TS_][HD_];
    __shared__ float vs[TS_][HD_];
    __shared__ float sc[TS_][TS_ + 1];
    int tid = threadIdx.x;
    int len = tgt_len[n]; if (len < 1) len = 1;

    for (int e = tid; e < TS_ * HD_; e += 256) {
        int t = e >> 6, d = e & 63;
        size_t off = (size_t)(t * 8 + n) * (3 * D_) + h * 64 + d;
        float q = 0.f, k = 0.f, v = 0.f;
#pragma unroll
        for (int z = 0; z < QKV_SPLIT; z++) {
            const float* b = qkv + (size_t)z * TOK_ * 3 * D_ + off;
            q += b[0]; k += b[512]; v += b[1024];
        }
        qs[t][d] = q; ks[t][d] = k; vs[t][d] = v;
    }
    __syncthreads();

    for (int p = tid; p < TS_ * TS_; p += 256) {
        int tq = p / TS_, tk = p - tq * TS_;
        float s;
        if (tk > tq || tk >= len) {
            s = -1e9f;
        } else {
            const float4* q4 = (const float4*)qs[tq];
            const float4* k4 = (const float4*)ks[tk];
            float s0 = 0.f, s1 = 0.f, s2 = 0.f, s3 = 0.f;
#pragma unroll
            for (int d = 0; d < HD_ / 4; d += 2) {
                float4 qa = q4[d], ka = k4[d];
                float4 qb = q4[d + 1], kb = k4[d + 1];
                s0 += qa.x * ka.x + qa.y * ka.y;
                s1 += qa.z * ka.z + qa.w * ka.w;
                s2 += qb.x * kb.x + qb.y * kb.y;
                s3 += qb.z * kb.z + qb.w * kb.w;
            }
            s = ((s0 + s1) + (s2 + s3)) * 0.125f;
        }
        sc[tq][tk] = s;
    }
    __syncthreads();

    {
        int w = tid >> 5, lane = tid & 31;
        for (int tq = w; tq < TS_; tq += 8) {
            float v0 = sc[tq][lane];
            float v1 = (lane == 0) ? sc[tq][32] : -1e30f;
            float mx = fmaxf(v0, v1);
#pragma unroll
            for (int off = 16; off > 0; off >>= 1)
                mx = fmaxf(mx, __shfl_xor_sync(0xffffffffu, mx, off));
            float e0 = expf(v0 - mx);
            float e1 = (lane == 0) ? expf(v1 - mx) : 0.f;
            float sum = e0 + e1;
#pragma unroll
            for (int off = 16; off > 0; off >>= 1)
                sum += __shfl_xor_sync(0xffffffffu, sum, off);
            float inv = 1.0f / sum;
            sc[tq][lane] = e0 * inv;
            if (lane == 0) sc[tq][32] = e1 * inv;
        }
    }
    __syncthreads();

    for (int e = tid; e < TS_ * HD_; e += 256) {
        int tq = e >> 6, d = e & 63;
        float s = 0.f;
#pragma unroll 11
        for (int tk = 0; tk < TS_; tk++) s += sc[tq][tk] * vs[tk][d];
        size_t idx = (size_t)(tq * 8 + n) * D_ + h * 64 + d;
        __nv_bfloat16 hv, lv;
        split_hl(s, hv, lv);
        oh[idx] = hv; ol[idx] = lv;
    }
}

// ---------------------------------------------------------------------------
// Residual add + LN
// ---------------------------------------------------------------------------
__global__ void add_ln_kernel(float* __restrict__ x,
                              const float* __restrict__ y, int nsplit,
                              const float* __restrict__ s,
                              const float* __restrict__ b,
                              __nv_bfloat16* __restrict__ xh,
                              __nv_bfloat16* __restrict__ xl) {
    int row = blockIdx.x, tid = threadIdx.x;
    __shared__ float sh[8];
    const float4 xv = ((const float4*)(x + (size_t)row * D_))[tid];
    float r0 = xv.x, r1 = xv.y, r2 = xv.z, r3 = xv.w;
    for (int z = 0; z < nsplit; z++) {
        const float4 yv = ((const float4*)(y + (size_t)z * TOK_ * D_ + (size_t)row * D_))[tid];
        r0 += yv.x; r1 += yv.y; r2 += yv.z; r3 += yv.w;
    }

    float sum = r0 + r1 + r2 + r3;
    int lane = tid & 31, wp = tid >> 5;
#pragma unroll
    for (int off = 16; off > 0; off >>= 1) sum += __shfl_xor_sync(0xffffffffu, sum, off);
    if (lane == 0) sh[wp] = sum;
    __syncthreads();
    float mean = (sh[0] + sh[1] + sh[2] + sh[3]) * (1.0f / 512.0f);

    float d0 = r0 - mean, d1 = r1 - mean, d2 = r2 - mean, d3 = r3 - mean;
    float sq = d0 * d0 + d1 * d1 + d2 * d2 + d3 * d3;
#pragma unroll
    for (int off = 16; off > 0; off >>= 1) sq += __shfl_xor_sync(0xffffffffu, sq, off);
    if (lane == 0) sh[4 + wp] = sq;
    __syncthreads();
    float var = (sh[4] + sh[5] + sh[6] + sh[7]) * (1.0f / 512.0f);
    float rstd = 1.0f / sqrtf(var + 1e-5f);

    const float4 sv = ((const float4*)s)[tid];
    const float4 bv = ((const float4*)b)[tid];
    float o0 = d0 * rstd * sv.x + bv.x;
    float o1 = d1 * rstd * sv.y + bv.y;
    float o2 = d2 * rstd * sv.z + bv.z;
    float o3 = d3 * rstd * sv.w + bv.w;
    ((float4*)(x + (size_t)row * D_))[tid] = make_float4(o0, o1, o2, o3);

    size_t base = (size_t)row * D_ + tid * 4;
    __nv_bfloat16 h0, h1, h2, h3, l0, l1, l2, l3;
    split_hl(o0, h0, l0); split_hl(o1, h1, l1);
    split_hl(o2, h2, l2); split_hl(o3, h3, l3);
    ((__nv_bfloat162*)(xh + base))[0] = __nv_bfloat162(h0, h1);
    ((__nv_bfloat162*)(xh + base))[1] = __nv_bfloat162(h2, h3);
    ((__nv_bfloat162*)(xl + base))[0] = __nv_bfloat162(l0, l1);
    ((__nv_bfloat162*)(xl + base))[1] = __nv_bfloat162(l2, l3);
}

// ---------------------------------------------------------------------------
// Joiner A materialization -> single fp16
// ---------------------------------------------------------------------------
__global__ void joiner_a_kernel(const float* __restrict__ enc,
                                const float* __restrict__ x,
                                __half* __restrict__ A) {
    int r = blockIdx.x;
    int n = r / (TI_ * TS_);
    int rem = r - n * (TI_ * TS_);
    int i = rem / TS_;
    int t = rem - i * TS_;
    const float4* er = (const float4*)(enc + (size_t)(i * 8 + n) * D_);
    const float4* xr = (const float4*)(x + (size_t)(t * 8 + n) * D_);
    int tid = threadIdx.x;
    float4 e = er[tid], xx = xr[tid];
    __half2 h0 = __half2(__float2half(tanhf(e.x + xx.x)), __float2half(tanhf(e.y + xx.y)));
    __half2 h1 = __half2(__float2half(tanhf(e.z + xx.z)), __float2half(tanhf(e.w + xx.w)));
    size_t base = (size_t)r * D_ + tid * 4;
    ((__half2*)(A + base))[0] = h0;
    ((__half2*)(A + base))[1] = h1;
}

// ---------------------------------------------------------------------------
// Joiner GEMM (tile 128x128, K=512, plain fp16, mma.sync)
// ---------------------------------------------------------------------------
__global__ void __launch_bounds__(256) joiner_tc_kernel(
    const __half* __restrict__ A,
    const __half* __restrict__ W,
    float* __restrict__ C) {
    extern __shared__ char smem[];
    const uint32_t sbase = smem_to_u32(smem);
    const int tid = threadIdx.x;
    const int n0 = blockIdx.x * 128;
    const int m0 = blockIdx.y * 128;

    const int w = tid >> 5, lane = tid & 31;
    const int wr = w >> 1, wc = w & 1;

    float acc[16][4];
#pragma unroll
    for (int i = 0; i < 16; i++)
#pragma unroll
        for (int j = 0; j < 4; j++) acc[i][j] = 0.f;

    const int nhalf = 16;
    load_half2_f16(A, W, m0, MJ_, n0, VP_, 0, sbase, tid, 0);
    cp_async_commit();
    for (int c = 0; c < nhalf; c++) {
        if (c + 1 < nhalf) {
            load_half2_f16(A, W, m0, MJ_, n0, VP_, (c + 1) * 32, sbase, tid, (c + 1) & 1);
            cp_async_commit();
            cp_async_wait<1>();
        } else {
            cp_async_wait<0>();
        }
        __syncthreads();
        mma_mainloop_half_f16(sbase, wr, wc, lane, acc, c & 1);
        __syncthreads();
    }

#pragma unroll
    for (int mi = 0; mi < 2; mi++) {
#pragma unroll
        for (int nt = 0; nt < 8; nt++) {
            int m = m0 + wr * 32 + mi * 16 + (lane >> 2);
            int ncol = n0 + wc * 64 + nt * 8 + 2 * (lane & 3);
            if (ncol < V_) {
                stg_cs_f2(C + (size_t)m * V_ + ncol,
                          acc[mi * 8 + nt][0], acc[mi * 8 + nt][1]);
                stg_cs_f2(C + (size_t)(m + 8) * V_ + ncol,
                          acc[mi * 8 + nt][2], acc[mi * 8 + nt][3]);
            }
        }
    }
}

// ---------------------------------------------------------------------------
// Host orchestration (single stream, R10 ordering)
// ---------------------------------------------------------------------------
extern "C" void kernel_launch(void* const* d_in, const int* in_sizes, int n_in,
                              void* d_out, int out_size) {
    const float* enc_out = (const float*)d_in[0];
    const float* embed_w = (const float*)d_in[1];
    const float* enc_w   = (const float*)d_in[2];
    const float* enc_b   = (const float*)d_in[3];
    const float* qkv_w   = (const float*)d_in[4];
    const float* qkv_b   = (const float*)d_in[5];
    const float* o_w     = (const float*)d_in[6];
    const float* o_b     = (const float*)d_in[7];
    const float* ln1_s   = (const float*)d_in[8];
    const float* ln1_b   = (const float*)d_in[9];
    const float* ff1_w   = (const float*)d_in[10];
    const float* ff1_b   = (const float*)d_in[11];
    const float* ff2_w   = (const float*)d_in[12];
    const float* ff2_b   = (const float*)d_in[13];
    const float* ln2_s   = (const float*)d_in[14];
    const float* ln2_b   = (const float*)d_in[15];
    const float* out_w   = (const float*)d_in[16];
    const int*   tgt_pad = (const int*)d_in[17];
    const int*   tgt_len = (const int*)d_in[18];
    const int*   sos     = (const int*)d_in[19];

    float *x, *qkv, *tmp, *encp;
    cudaGetSymbolAddress((void**)&x, g_x);
    cudaGetSymbolAddress((void**)&qkv, g_qkv);
    cudaGetSymbolAddress((void**)&tmp, g_tmp);
    cudaGetSymbolAddress((void**)&encp, g_encp);

    __nv_bfloat16 *xh, *xl, *ath, *atl, *fh, *fl;
    cudaGetSymbolAddress((void**)&xh, g_xh);
    cudaGetSymbolAddress((void**)&xl, g_xl);
    cudaGetSymbolAddress((void**)&ath, g_ath);
    cudaGetSymbolAddress((void**)&atl, g_atl);
    cudaGetSymbolAddress((void**)&fh, g_fh);
    cudaGetSymbolAddress((void**)&fl, g_fl);

    __nv_bfloat16 *qkvwh, *qkvwl, *owh, *owl, *f1h, *f1l, *f2h, *f2l;
    cudaGetSymbolAddress((void**)&qkvwh, g_qkvwh);
    cudaGetSymbolAddress((void**)&qkvwl, g_qkvwl);
    cudaGetSymbolAddress((void**)&owh, g_owh);
    cudaGetSymbolAddress((void**)&owl, g_owl);
    cudaGetSymbolAddress((void**)&f1h, g_f1h);
    cudaGetSymbolAddress((void**)&f1l, g_f1l);
    cudaGetSymbolAddress((void**)&f2h, g_f2h);
    cudaGetSymbolAddress((void**)&f2l, g_f2l);

    __half *exf, *ewf, *Aj, *Wj;
    cudaGetSymbolAddress((void**)&exf, g_exf);
    cudaGetSymbolAddress((void**)&ewf, g_ewf);
    cudaGetSymbolAddress((void**)&Aj, g_Aj);
    cudaGetSymbolAddress((void**)&Wj, g_Wj);

    static bool attr_done = false;
    if (!attr_done) {
        cudaFuncSetAttribute(joiner_tc_kernel,
                             cudaFuncAttributeMaxDynamicSharedMemorySize, JJ_SMEM);
        cudaFuncSetAttribute(gemm_f16,
                             cudaFuncAttributeMaxDynamicSharedMemorySize, JJ_SMEM);
        cudaFuncSetAttribute(gemm_tc,
                             cudaFuncAttributeMaxDynamicSharedMemorySize, JT_SMEM);
        attr_done = true;
    }

    // ---- weight splits (bf16 hi/lo for the chain) + fp16 conversions ----
    {
        SplitJobs jobs;
        int c0 = L_ * 3 * D_ * D_ / 4;
        int c1 = L_ * D_ * D_ / 4;
        int c2 = L_ * FF_ * D_ / 4;
        int c3 = L_ * D_ * FF_ / 4;
        jobs.src[0] = qkv_w;  jobs.h[0] = qkvwh; jobs.l[0] = qkvwl; jobs.end[0] = c0;
        jobs.src[1] = o_w;    jobs.h[1] = owh;   jobs.l[1] = owl;   jobs.end[1] = jobs.end[0] + c1;
        jobs.src[2] = ff1_w;  jobs.h[2] = f1h;   jobs.l[2] = f1l;   jobs.end[2] = jobs.end[1] + c2;
        jobs.src[3] = ff2_w;  jobs.h[3] = f2h;   jobs.l[3] = f2l;   jobs.end[3] = jobs.end[2] + c3;
        int total = jobs.end[3];
        split_all_kernel<<<(total + 255) / 256, 256>>>(jobs, total);
        int nconv = (TI_ * NB_ * D_ + D_ * D_) / 4;
        enc_f16_kernel<<<(nconv + 255) / 256, 256>>>(enc_out, enc_w, exf, ewf);
        w_split_kernel<<<VP_, 128>>>(out_w, Wj);
    }

    // enc projection: fp16 single-term GEMM (3x less MMA, 2x fewer loads)
    gemm_f16<<<dim3(D_ / 128, (TI_ * NB_) / 128), 256, JJ_SMEM>>>(
        exf, ewf, enc_b, encp, TI_ * NB_, D_);

    // embedding + positions
    embed_kernel<<<TOK_, 128>>>(embed_w, tgt_pad, sos, x, xh, xl);

    // 6 post-norm transformer layers (R10-best config)
    for (int l = 0; l < L_; l++) {
        gemm_tc<<<dim3(3 * D_ / 128, 3, QKV_SPLIT), 256, JT_SMEM>>>(
            xh, xl, qkvwh + (size_t)l * 3 * D_ * D_, qkvwl + (size_t)l * 3 * D_ * D_,
            qkv_b + (size_t)l * 3 * D_, qkv, nullptr, nullptr,
            TOK_, 3 * D_, D_, 8 / QKV_SPLIT, 0);
        attention_kernel<<<NB_ * H_, 256>>>(qkv, tgt_len, ath, atl);
        gemm_tc<<<dim3(D_ / 128, 3, O_SPLIT), 256, JT_SMEM>>>(
            ath, atl, owh + (size_t)l * D_ * D_, owl + (size_t)l * D_ * D_,
            o_b + (size_t)l * D_, tmp, nullptr, nullptr,
            TOK_, D_, D_, 8 / O_SPLIT, 0);
        add_ln_kernel<<<TOK_, 128>>>(x, tmp, O_SPLIT,
            ln1_s + (size_t)l * D_, ln1_b + (size_t)l * D_, xh, xl);
        gemm_tc<<<dim3(FF_ / 128, 3, 1), 256, JT_SMEM>>>(
            xh, xl, f1h + (size_t)l * FF_ * D_, f1l + (size_t)l * FF_ * D_,
            ff1_b + (size_t)l * FF_, nullptr, fh, fl,
            TOK_, FF_, D_, 8, 1);
        gemm_tc<<<dim3(D_ / 128, 3, FF2_SPLIT), 256, JT_SMEM>>>(
            fh, fl, f2h + (size_t)l * D_ * FF_, f2l + (size_t)l * D_ * FF_,
            ff2_b + (size_t)l * D_, tmp, nullptr, nullptr,
            TOK_, D_, FF_, FF_ / 64 / FF2_SPLIT, 0);
        add_ln_kernel<<<TOK_, 128>>>(x, tmp, FF2_SPLIT,
            ln2_s + (size_t)l * D_, ln2_b + (size_t)l * D_, xh, xl);
    }

    // joiner
    joiner_a_kernel<<<MJ_, 128>>>(encp, x, Aj);
    joiner_tc_kernel<<<dim3(VP_ / 128, MJ_ / 128), 256, JJ_SMEM>>>(
        Aj, Wj, (float*)d_out);
}

// round 16
// speedup vs baseline: 1.1415x; 1.1415x over previous
#include <cuda_runtime.h>
#include <cuda_bf16.h>
#include <cuda_fp16.h>
#include <math.h>
#include <stdint.h>

#if defined(__CUDA_ARCH_FEAT_SM103_ALL) || defined(__CUDA_ARCH_FEAT_SM100_ALL) || defined(__CUDA_ARCH_FEAT_SM101_ALL)
#define USE_TCGEN05 1
#else
#define USE_TCGEN05 0
#endif

// ---------------------------------------------------------------------------
// Problem constants
// ---------------------------------------------------------------------------
#define TI_   128
#define NB_   8
#define TO_   32
#define TS_   33
#define D_    512
#define H_    8
#define HD_   64
#define FF_   2048
#define V_    2000
#define VP_   2048
#define L_    6
#define TOK_  (TS_ * NB_)          // 264
#define MJ_   (NB_ * TI_ * TS_)    // 33792
#define FF2_SPLIT 8
#define QKV_SPLIT 4
#define O_SPLIT   4

// ---------------------------------------------------------------------------
// Scratch
// ---------------------------------------------------------------------------
__device__ float g_x[TOK_ * D_];
__device__ float g_qkv[QKV_SPLIT * TOK_ * 3 * D_];
__device__ float g_tmp[FF2_SPLIT * TOK_ * D_];
__device__ float g_encp[TI_ * NB_ * D_];

__device__ __nv_bfloat16 g_xh[TOK_ * D_],  g_xl[TOK_ * D_];
__device__ __nv_bfloat16 g_ath[TOK_ * D_], g_atl[TOK_ * D_];
__device__ __nv_bfloat16 g_fh[TOK_ * FF_], g_fl[TOK_ * FF_];

__device__ __nv_bfloat16 g_qkvwh[(size_t)L_ * 3 * D_ * D_], g_qkvwl[(size_t)L_ * 3 * D_ * D_];
__device__ __nv_bfloat16 g_owh[(size_t)L_ * D_ * D_],       g_owl[(size_t)L_ * D_ * D_];
__device__ __nv_bfloat16 g_f1h[(size_t)L_ * FF_ * D_],      g_f1l[(size_t)L_ * FF_ * D_];
__device__ __nv_bfloat16 g_f2h[(size_t)L_ * D_ * FF_],      g_f2l[(size_t)L_ * D_ * FF_];
__device__ __nv_bfloat16 g_ewh[D_ * D_],                    g_ewl[D_ * D_];
__device__ __nv_bfloat16 g_exh[TI_ * NB_ * D_],             g_exl[TI_ * NB_ * D_];

__device__ __half g_Aj[(size_t)MJ_ * D_];
__device__ __half g_Wj[(size_t)VP_ * D_];

// ---------------------------------------------------------------------------
// PTX helpers
// ---------------------------------------------------------------------------
__device__ __forceinline__ uint32_t elect_one_pred() {
    uint32_t pred;
    asm volatile(
        "{\n\t.reg .pred p;\n\telect.sync _|p, 0xFFFFFFFF;\n\t"
        "selp.b32 %0, 1, 0, p;\n\t}"
        : "=r"(pred));
    return pred;
}
__device__ __forceinline__ uint32_t smem_to_u32(const void* smem_ptr) {
    uint32_t addr;
    asm("{ .reg .u64 tmp; cvta.to.shared.u64 tmp, %1; cvt.u32.u64 %0, tmp; }"
        : "=r"(addr) : "l"(smem_ptr));
    return addr;
}
__device__ __forceinline__ uint32_t sw_off(uint32_t bo) {
    return bo ^ ((bo >> 3) & 0x70);
}
__device__ __forceinline__ void cp_async16(uint32_t saddr, const void* gptr, int valid) {
    asm volatile("cp.async.cg.shared.global [%0], [%1], 16, %2;"
        :: "r"(saddr), "l"(gptr), "r"(valid ? 16 : 0));
}
__device__ __forceinline__ void cp_async_commit() {
    asm volatile("cp.async.commit_group;");
}
template <int N>
__device__ __forceinline__ void cp_async_wait() {
    asm volatile("cp.async.wait_group %0;" :: "n"(N) : "memory");
}
__device__ __forceinline__ void stg_cs_f2(float* p, float a, float b) {
    asm volatile("st.global.cs.v2.f32 [%0], {%1,%2};" :: "l"(p), "f"(a), "f"(b) : "memory");
}
__device__ __forceinline__ void stg_cs_f4(float* p, float a, float b, float c, float d) {
    asm volatile("st.global.cs.v4.f32 [%0], {%1,%2,%3,%4};"
        :: "l"(p), "f"(a), "f"(b), "f"(c), "f"(d) : "memory");
}
__device__ __forceinline__ void stg_cs_f1(float* p, float a) {
    asm volatile("st.global.cs.f32 [%0], %1;" :: "l"(p), "f"(a) : "memory");
}

static constexpr uint64_t SMEM_DESC_BASE_SW128 =
    (uint64_t(2)  << 61) | (uint64_t(1) << 46) | (uint64_t(64) << 32) | (uint64_t(1) << 16);
#define MAKE_SMEM_DESC(base_addr) \
    (SMEM_DESC_BASE_SW128 | ((uint64_t)((base_addr) >> 4) & 0x3FFF))

#if USE_TCGEN05
#define TCGEN05_ALLOC(smem_result_addr, nCols) \
    asm volatile("tcgen05.alloc.cta_group::1.sync.aligned.shared::cta.b32 [%0], %1;" \
        :: "r"((uint32_t)(smem_result_addr)), "r"((uint32_t)(nCols)) : "memory")
#define TCGEN05_DEALLOC(tmem_addr, nCols) \
    asm volatile("tcgen05.dealloc.cta_group::1.sync.aligned.b32 %0, %1;" \
        :: "r"(tmem_addr), "r"((uint32_t)(nCols)))
#define TCGEN05_RELINQUISH_ALLOC_PERMIT() \
    asm volatile("tcgen05.relinquish_alloc_permit.cta_group::1.sync.aligned;")
#define TCGEN05_COMMIT(mbar_smem_addr) \
    asm volatile("tcgen05.commit.cta_group::1.mbarrier::arrive::one.shared::cluster.b64 [%0];" \
        :: "r"((uint32_t)(mbar_smem_addr)) : "memory")
#define TCGEN05_WAIT_LD() \
    asm volatile("tcgen05.wait::ld.sync.aligned;" ::: "memory")
#define TCGEN05_FENCE_AFTER() \
    asm volatile("tcgen05.fence::after_thread_sync;" ::: "memory")
#define FENCE_PROXY_ASYNC_SHARED_CTA() \
    asm volatile("fence.proxy.async.shared::cta;" ::: "memory")
#define MBARRIER_INIT(mbar_smem_addr, count) \
    asm volatile("mbarrier.init.shared.b64 [%0], %1;" \
        :: "r"((uint32_t)(mbar_smem_addr)), "r"((uint32_t)(count)) : "memory")
#define MBARRIER_INVAL(mbar_smem_addr) \
    asm volatile("mbarrier.inval.shared.b64 [%0];" :: "r"((uint32_t)(mbar_smem_addr)) : "memory")
#define MBARRIER_WAIT_PARITY(mbar_smem_addr, phase_parity) do { \
    uint32_t _mbar = (uint32_t)(mbar_smem_addr); \
    uint32_t _parity = (uint32_t)(phase_parity); \
    uint32_t _done; \
    asm volatile( \
        "{\n\t.reg .pred p;\n\t" \
        "mbarrier.try_wait.parity.acquire.cta.shared::cta.b64 p, [%1], %2;\n\t" \
        "selp.b32 %0, 1, 0, p;\n\t}" \
        : "=r"(_done) : "r"(_mbar), "r"(_parity) : "memory"); \
    if (!_done) { \
        asm volatile( \
            "{\n\t.reg .pred P1;\n\t" \
            "WAIT_LOOP_%=:\n\t" \
            "mbarrier.try_wait.parity.acquire.cta.shared::cta.b64 P1, [%0], %1, 0x989680;\n\t" \
            "@P1 bra.uni WAIT_DONE_%=;\n\t" \
            "bra.uni WAIT_LOOP_%=;\n\t" \
            "WAIT_DONE_%=:\n\t}" \
            :: "r"(_mbar), "r"(_parity) : "memory"); \
    } \
} while(0)
#define TCGEN05_LD_32X32B_X32(r, tmem_addr) \
    asm volatile( \
        "tcgen05.ld.sync.aligned.32x32b.x32.b32 " \
        "{%0, %1, %2, %3, %4, %5, %6, %7, " \
        " %8, %9, %10, %11, %12, %13, %14, %15, " \
        " %16, %17, %18, %19, %20, %21, %22, %23, " \
        " %24, %25, %26, %27, %28, %29, %30, %31}, [%32];" \
        : "=r"((r)[0]),  "=r"((r)[1]),  "=r"((r)[2]),  "=r"((r)[3]), \
          "=r"((r)[4]),  "=r"((r)[5]),  "=r"((r)[6]),  "=r"((r)[7]), \
          "=r"((r)[8]),  "=r"((r)[9]),  "=r"((r)[10]), "=r"((r)[11]), \
          "=r"((r)[12]), "=r"((r)[13]), "=r"((r)[14]), "=r"((r)[15]), \
          "=r"((r)[16]), "=r"((r)[17]), "=r"((r)[18]), "=r"((r)[19]), \
          "=r"((r)[20]), "=r"((r)[21]), "=r"((r)[22]), "=r"((r)[23]), \
          "=r"((r)[24]), "=r"((r)[25]), "=r"((r)[26]), "=r"((r)[27]), \
          "=r"((r)[28]), "=r"((r)[29]), "=r"((r)[30]), "=r"((r)[31]) \
        : "r"(tmem_addr))

__device__ __forceinline__ void mma_f16_ss_cg1(uint32_t d_tmem, uint64_t a_desc,
                                               uint64_t b_desc, uint32_t idesc,
                                               uint32_t enable) {
    asm volatile(
        "{\n\t.reg .pred p;\n\t"
        "setp.ne.u32 p, %4, 0;\n\t"
        "tcgen05.mma.cta_group::1.kind::f16 [%0], %1, %2, %3, {%5, %5, %5, %5}, p;\n\t}"
        :: "r"(d_tmem), "l"(a_desc), "l"(b_desc), "r"(idesc), "r"(enable), "r"(0u)
        : "memory");
}
#define JOINER_IDESC_F16 0x8200010u
#endif // USE_TCGEN05

// ---------------------------------------------------------------------------
// mma.sync helpers
// ---------------------------------------------------------------------------
__device__ __forceinline__ void ldmatrix_x4(uint32_t* r, uint32_t addr) {
    asm volatile("ldmatrix.sync.aligned.m8n8.x4.shared.b16 {%0,%1,%2,%3}, [%4];"
        : "=r"(r[0]), "=r"(r[1]), "=r"(r[2]), "=r"(r[3]) : "r"(addr));
}
__device__ __forceinline__ void mma16816(float* d, const uint32_t* a,
                                         uint32_t b0, uint32_t b1) {
    asm volatile(
        "mma.sync.aligned.m16n8k16.row.col.f32.bf16.bf16.f32 "
        "{%0,%1,%2,%3}, {%4,%5,%6,%7}, {%8,%9}, {%0,%1,%2,%3};"
        : "+f"(d[0]), "+f"(d[1]), "+f"(d[2]), "+f"(d[3])
        : "r"(a[0]), "r"(a[1]), "r"(a[2]), "r"(a[3]), "r"(b0), "r"(b1));
}
__device__ __forceinline__ void mma16816_f16(float* d, const uint32_t* a,
                                             uint32_t b0, uint32_t b1) {
    asm volatile(
        "mma.sync.aligned.m16n8k16.row.col.f32.f16.f16.f32 "
        "{%0,%1,%2,%3}, {%4,%5,%6,%7}, {%8,%9}, {%0,%1,%2,%3};"
        : "+f"(d[0]), "+f"(d[1]), "+f"(d[2]), "+f"(d[3])
        : "r"(a[0]), "r"(a[1]), "r"(a[2]), "r"(a[3]), "r"(b0), "r"(b1));
}

__device__ __forceinline__ void split_hl(float v, __nv_bfloat16& h, __nv_bfloat16& l) {
    h = __float2bfloat16(v);
    l = __float2bfloat16(v - __bfloat162float(h));
}

// ---------------------------------------------------------------------------
// Fused weight split
// ---------------------------------------------------------------------------
#define NSPLITJOBS 6
struct SplitJobs {
    const float* src[NSPLITJOBS];
    __nv_bfloat16* h[NSPLITJOBS];
    __nv_bfloat16* l[NSPLITJOBS];
    int end[NSPLITJOBS];
};

__global__ void split_all_kernel(SplitJobs jobs, int total) {
    int i = blockIdx.x * blockDim.x + threadIdx.x;
    if (i >= total) return;
    int j = 0;
#pragma unroll
    for (int k = 0; k < NSPLITJOBS - 1; k++) j += (i >= jobs.end[k]);
    int base = (j == 0) ? 0 : jobs.end[j - 1];
    int li = i - base;
    float4 w = ((const float4*)jobs.src[j])[li];
    __nv_bfloat16 h0, h1, h2, h3, l0, l1, l2, l3;
    split_hl(w.x, h0, l0); split_hl(w.y, h1, l1);
    split_hl(w.z, h2, l2); split_hl(w.w, h3, l3);
    ((__nv_bfloat162*)jobs.h[j])[2 * li]     = __nv_bfloat162(h0, h1);
    ((__nv_bfloat162*)jobs.h[j])[2 * li + 1] = __nv_bfloat162(h2, h3);
    ((__nv_bfloat162*)jobs.l[j])[2 * li]     = __nv_bfloat162(l0, l1);
    ((__nv_bfloat162*)jobs.l[j])[2 * li + 1] = __nv_bfloat162(l2, l3);
}

__global__ void w_split_kernel(const float* __restrict__ W,
                               __half* __restrict__ Wj) {
    int r = blockIdx.x;
    int tid = threadIdx.x;
    size_t base = (size_t)r * D_ + tid * 4;
    if (r < V_) {
        const float4 w = ((const float4*)(W + (size_t)r * D_))[tid];
        ((__half2*)(Wj + base))[0] = __half2(__float2half(w.x), __float2half(w.y));
        ((__half2*)(Wj + base))[1] = __half2(__float2half(w.z), __float2half(w.w));
    } else {
        __half2 z = __half2(__float2half(0.f), __float2half(0.f));
        ((__half2*)(Wj + base))[0] = z;
        ((__half2*)(Wj + base))[1] = z;
    }
}

// ---------------------------------------------------------------------------
// Embedding + positions
// ---------------------------------------------------------------------------
__global__ void embed_kernel(const float* __restrict__ embed,
                             const int* __restrict__ tgt_pad,
                             const int* __restrict__ sos,
                             float* __restrict__ x,
                             __nv_bfloat16* __restrict__ xh,
                             __nv_bfloat16* __restrict__ xl) {
    int r = blockIdx.x;
    int t = r >> 3, n = r & 7;
    int tok = (t == 0) ? sos[0] : tgt_pad[n * TO_ + (t - 1)];
    const float* e = embed + (size_t)tok * D_;
    const float sc = sqrtf(512.0f);
    int tid = threadIdx.x;
#pragma unroll
    for (int i = 0; i < 2; i++) {
        int d = tid * 4 + i * 2;
        float ddiv = expf((float)d * (-9.210340371976184f / 512.0f));
        float ang = (float)t * ddiv;
        float sv, cv;
        sincosf(ang, &sv, &cv);
        size_t idx = (size_t)r * D_ + d;
        float v0 = e[d] * sc + sv;
        float v1 = e[d + 1] * sc + cv;
        x[idx] = v0; x[idx + 1] = v1;
        __nv_bfloat16 h0, l0, h1, l1;
        split_hl(v0, h0, l0); split_hl(v1, h1, l1);
        xh[idx] = h0; xh[idx + 1] = h1;
        xl[idx] = l0; xl[idx + 1] = l1;
    }
}

// ---------------------------------------------------------------------------
// Tile loaders
// ---------------------------------------------------------------------------
__device__ __forceinline__ void tc_load_tile_async(const __nv_bfloat16* __restrict__ src,
                                                   int row0, int maxrow, int koff,
                                                   int kstride, uint32_t sm, int tid) {
#pragma unroll
    for (int p = 0; p < 4; p++) {
        int idx = p * 256 + tid;
        int row = idx >> 3, seg = idx & 7;
        int gr = row0 + row;
        uint32_t bo = (uint32_t)(row * 128 + seg * 16);
        cp_async16(sm + sw_off(bo),
                   src + (size_t)gr * kstride + koff + seg * 8,
                   gr < maxrow);
    }
}
__device__ __forceinline__ void tc_load_half_async(const __nv_bfloat16* __restrict__ src,
                                                   int row0, int maxrow, int kelem,
                                                   int kstride, uint32_t sm, int tid, int p) {
#pragma unroll
    for (int q = 0; q < 2; q++) {
        int idx = q * 256 + tid;
        int row = idx >> 2, seg = idx & 3;
        int gr = row0 + row;
        uint32_t bo = (uint32_t)(row * 128 + p * 64 + seg * 16);
        cp_async16(sm + sw_off(bo),
                   src + (size_t)gr * kstride + kelem + seg * 8,
                   gr < maxrow);
    }
}

// layer-chain GEMM smem layout (bf16 3-term)
#define JT_BUF      16384
#define JT_SM_AH    1024
#define JT_SM_AL    (JT_SM_AH + JT_BUF)
#define JT_SM_WH    (JT_SM_AL + JT_BUF)
#define JT_SM_WL    (JT_SM_WH + JT_BUF)
#define JT_SMEM     (JT_SM_WL + JT_BUF)      // 66560

// joiner smem layouts
#define JJ_STAGE    32768
#define JJ_SM_A(s)  (1024 + (s) * JJ_STAGE)
#define JJ_SM_W(s)  (1024 + (s) * JJ_STAGE + JT_BUF)
#define JJ_SMEM_LAUNCH (1024 + 2 * JJ_STAGE)  // 66560

__device__ __forceinline__ void load_half4(const __nv_bfloat16* Ah, const __nv_bfloat16* Al,
                                           const __nv_bfloat16* Wh, const __nv_bfloat16* Wl,
                                           int m0, int M, int n0, int N,
                                           int kelem, int kstride,
                                           uint32_t sbase, int tid, int p) {
    tc_load_half_async(Ah, m0, M, kelem, kstride, sbase + JT_SM_AH, tid, p);
    tc_load_half_async(Al, m0, M, kelem, kstride, sbase + JT_SM_AL, tid, p);
    tc_load_half_async(Wh, n0, N, kelem, kstride, sbase + JT_SM_WH, tid, p);
    tc_load_half_async(Wl, n0, N, kelem, kstride, sbase + JT_SM_WL, tid, p);
}
__device__ __forceinline__ void load_half2_j(const __half* A, const __half* W,
                                             int m0, int n0, int kelem,
                                             uint32_t sbase, int tid, int p) {
    tc_load_half_async((const __nv_bfloat16*)A, m0, MJ_, kelem, D_, sbase + JJ_SM_A(0), tid, p);
    tc_load_half_async((const __nv_bfloat16*)W, n0, VP_, kelem, D_, sbase + JJ_SM_W(0), tid, p);
}

// ---------------------------------------------------------------------------
// Chain mainloop with A-fragment hoist
// ---------------------------------------------------------------------------
__device__ __forceinline__ void mma_mainloop_half(uint32_t sbase, int wr, int wc,
                                                  int lane, float acc[16][4], int p) {
    const int boffs[3] = {JT_SM_WH, JT_SM_WL, JT_SM_WH};
    const int bt = lane >> 3, br_ = lane & 7;
#pragma unroll
    for (int si = 0; si < 2; si++) {
        const int s = 2 * p + si;
        uint32_t AH[2][4], AL[2][4];
#pragma unroll
        for (int mi = 0; mi < 2; mi++) {
            uint32_t bo = (uint32_t)((wr * 32 + mi * 16 + (lane & 15)) * 128
                                     + s * 32 + (lane >> 4) * 16);
            ldmatrix_x4(AH[mi], sbase + JT_SM_AH + sw_off(bo));
            ldmatrix_x4(AL[mi], sbase + JT_SM_AL + sw_off(bo));
        }
#pragma unroll
        for (int tm = 0; tm < 3; tm++) {
            const uint32_t (*af)[4] = (tm == 2) ? AL : AH;
#pragma unroll
            for (int g = 0; g < 4; g++) {
                uint32_t bo = (uint32_t)((wc * 64 + g * 16 + (bt >> 1) * 8 + br_) * 128
                                         + s * 32 + (bt & 1) * 16);
                uint32_t bfr[4];
                ldmatrix_x4(bfr, sbase + boffs[tm] + sw_off(bo));
                mma16816(acc[2 * g],     af[0], bfr[0], bfr[1]);
                mma16816(acc[8 + 2 * g], af[1], bfr[0], bfr[1]);
                mma16816(acc[2 * g + 1],     af[0], bfr[2], bfr[3]);
                mma16816(acc[8 + 2 * g + 1], af[1], bfr[2], bfr[3]);
            }
        }
    }
}
__device__ __forceinline__ void mma_mainloop_half_j(uint32_t sbase, int wr, int wc,
                                                    int lane, float acc[16][4], int p) {
    const int bt = lane >> 3, br_ = lane & 7;
#pragma unroll
    for (int si = 0; si < 2; si++) {
        const int s = 2 * p + si;
        uint32_t afrag[2][4];
#pragma unroll
        for (int mi = 0; mi < 2; mi++) {
            uint32_t bo = (uint32_t)((wr * 32 + mi * 16 + (lane & 15)) * 128
                                     + s * 32 + (lane >> 4) * 16);
            ldmatrix_x4(afrag[mi], sbase + JJ_SM_A(0) + sw_off(bo));
        }
#pragma unroll
        for (int g = 0; g < 4; g++) {
            uint32_t bo = (uint32_t)((wc * 64 + g * 16 + (bt >> 1) * 8 + br_) * 128
                                     + s * 32 + (bt & 1) * 16);
            uint32_t bfr[4];
            ldmatrix_x4(bfr, sbase + JJ_SM_W(0) + sw_off(bo));
            mma16816_f16(acc[2 * g],     afrag[0], bfr[0], bfr[1]);
            mma16816_f16(acc[8 + 2 * g], afrag[1], bfr[0], bfr[1]);
            mma16816_f16(acc[2 * g + 1],     afrag[0], bfr[2], bfr[3]);
            mma16816_f16(acc[8 + 2 * g + 1], afrag[1], bfr[2], bfr[3]);
        }
    }
}

// ---------------------------------------------------------------------------
// Layer-chain tensor GEMM (3-term bf16 hi/lo), half-buffer pipelined
// ---------------------------------------------------------------------------
__global__ void __launch_bounds__(256) gemm_tc(
    const __nv_bfloat16* __restrict__ Ah, const __nv_bfloat16* __restrict__ Al,
    const __nv_bfloat16* __restrict__ Wh, const __nv_bfloat16* __restrict__ Wl,
    const float* __restrict__ bias,
    float* __restrict__ C,
    __nv_bfloat16* __restrict__ Ch, __nv_bfloat16* __restrict__ Cl,
    int M, int N, int kstride, int chunks, int relu) {
    extern __shared__ char smem[];
    const uint32_t sbase = smem_to_u32(smem);
    const int tid = threadIdx.x;
    const int n0 = blockIdx.x * 128;
    const int m0 = blockIdx.y * 128;
    const int z  = blockIdx.z;
    const int koff0 = z * chunks * 64;
    if (C) C += (size_t)z * M * N;

    const int w = tid >> 5, lane = tid & 31;
    const int wr = w >> 1, wc = w & 1;

    float acc[16][4];
#pragma unroll
    for (int i = 0; i < 16; i++)
#pragma unroll
        for (int j = 0; j < 4; j++) acc[i][j] = 0.f;

    const int nhalf = chunks * 2;
    load_half4(Ah, Al, Wh, Wl, m0, M, n0, N, koff0, kstride, sbase, tid, 0);
    cp_async_commit();
    for (int c = 0; c < nhalf; c++) {
        if (c + 1 < nhalf) {
            load_half4(Ah, Al, Wh, Wl, m0, M, n0, N,
                       koff0 + (c + 1) * 32, kstride, sbase, tid, (c + 1) & 1);
            cp_async_commit();
            cp_async_wait<1>();
        } else {
            cp_async_wait<0>();
        }
        __syncthreads();
        mma_mainloop_half(sbase, wr, wc, lane, acc, c & 1);
        __syncthreads();
    }

    const bool addb = (bias != nullptr) && (z == 0);
#pragma unroll
    for (int mi = 0; mi < 2; mi++) {
#pragma unroll
        for (int nt = 0; nt < 8; nt++) {
            int m = m0 + wr * 32 + mi * 16 + (lane >> 2);
            int ncol = n0 + wc * 64 + nt * 8 + 2 * (lane & 3);
            float b0v = addb ? bias[ncol] : 0.f;
            float b1v = addb ? bias[ncol + 1] : 0.f;
            float v0 = acc[mi * 8 + nt][0] + b0v;
            float v1 = acc[mi * 8 + nt][1] + b1v;
            float v2 = acc[mi * 8 + nt][2] + b0v;
            float v3 = acc[mi * 8 + nt][3] + b1v;
            if (relu) {
                v0 = fmaxf(v0, 0.f); v1 = fmaxf(v1, 0.f);
                v2 = fmaxf(v2, 0.f); v3 = fmaxf(v3, 0.f);
            }
            if (m < M) {
                size_t o = (size_t)m * N + ncol;
                if (C) *(float2*)(C + o) = make_float2(v0, v1);
                if (Ch) {
                    __nv_bfloat16 h0, h1, l0, l1;
                    split_hl(v0, h0, l0); split_hl(v1, h1, l1);
                    *(__nv_bfloat162*)(Ch + o) = __nv_bfloat162(h0, h1);
                    *(__nv_bfloat162*)(Cl + o) = __nv_bfloat162(l0, l1);
                }
            }
            if (m + 8 < M) {
                size_t o = (size_t)(m + 8) * N + ncol;
                if (C) *(float2*)(C + o) = make_float2(v2, v3);
                if (Ch) {
                    __nv_bfloat16 h0, h1, l0, l1;
                    split_hl(v2, h0, l0); split_hl(v3, h1, l1);
                    *(__nv_bfloat162*)(Ch + o) = __nv_bfloat162(h0, h1);
                    *(__nv_bfloat162*)(Cl + o) = __nv_bfloat162(l0, l1);
                }
            }
        }
    }
}

// ---------------------------------------------------------------------------
// Attention v2: 256 threads, warp-parallel softmax, vectorized dot products
// ---------------------------------------------------------------------------
__global__ void __launch_bounds__(256) attention_kernel(
    const float* __restrict__ qkv,
    const int* __restrict__ tgt_len,
    __nv_bfloat16* __restrict__ oh,
    __nv_bfloat16* __restrict__ ol) {
    int n = blockIdx.x >> 3, h = blockIdx.x & 7;
    __shared__ float qs[TS_][HD_];
    __shared__ float ks[TS_][HD_];
    __shared__ float vs[TS_][HD_];
    __shared__ float sc[TS_][TS_ + 1];
    int tid = threadIdx.x;   // 256
    int len = tgt_len[n]; if (len < 1) len = 1;

    for (int e = tid; e < TS_ * HD_; e += 256) {
        int t = e >> 6, d = e & 63;
        size_t off = (size_t)(t * 8 + n) * (3 * D_) + h * 64 + d;
        float q = 0.f, k = 0.f, v = 0.f;
#pragma unroll
        for (int z = 0; z < QKV_SPLIT; z++) {
            const float* b = qkv + (size_t)z * TOK_ * 3 * D_ + off;
            q += b[0]; k += b[512]; v += b[1024];
        }
        qs[t][d] = q; ks[t][d] = k; vs[t][d] = v;
    }
    __syncthreads();

    for (int p = tid; p < TS_ * TS_; p += 256) {
        int tq = p / TS_, tk = p - tq * TS_;
        float s;
        if (tk > tq || tk >= len) {
            s = -1e9f;
        } else {
            const float4* q4 = (const float4*)qs[tq];
            const float4* k4 = (const float4*)ks[tk];
            float s0 = 0.f, s1 = 0.f, s2 = 0.f, s3 = 0.f;
#pragma unroll
            for (int d = 0; d < HD_ / 4; d += 2) {
                float4 qa = q4[d], ka = k4[d];
                float4 qb = q4[d + 1], kb = k4[d + 1];
                s0 += qa.x * ka.x + qa.y * ka.y;
                s1 += qa.z * ka.z + qa.w * ka.w;
                s2 += qb.x * kb.x + qb.y * kb.y;
                s3 += qb.z * kb.z + qb.w * kb.w;
            }
            s = ((s0 + s1) + (s2 + s3)) * 0.125f;
        }
        sc[tq][tk] = s;
    }
    __syncthreads();

    {
        int w = tid >> 5, lane = tid & 31;
        for (int tq = w; tq < TS_; tq += 8) {
            float v0 = sc[tq][lane];
            float v1 = (lane == 0) ? sc[tq][32] : -1e30f;
            float mx = fmaxf(v0, v1);
#pragma unroll
            for (int off = 16; off > 0; off >>= 1)
                mx = fmaxf(mx, __shfl_xor_sync(0xffffffffu, mx, off));
            float e0 = expf(v0 - mx);
            float e1 = (lane == 0) ? expf(v1 - mx) : 0.f;
            float sum = e0 + e1;
#pragma unroll
            for (int off = 16; off > 0; off >>= 1)
                sum += __shfl_xor_sync(0xffffffffu, sum, off);
            float inv = 1.0f / sum;
            sc[tq][lane] = e0 * inv;
            if (lane == 0) sc[tq][32] = e1 * inv;
        }
    }
    __syncthreads();

    for (int e = tid; e < TS_ * HD_; e += 256) {
        int tq = e >> 6, d = e & 63;
        float s = 0.f;
#pragma unroll 11
        for (int tk = 0; tk < TS_; tk++) s += sc[tq][tk] * vs[tk][d];
        size_t idx = (size_t)(tq * 8 + n) * D_ + h * 64 + d;
        __nv_bfloat16 hv, lv;
        split_hl(s, hv, lv);
        oh[idx] = hv; ol[idx] = lv;
    }
}

// ---------------------------------------------------------------------------
// Residual add + LN
// ---------------------------------------------------------------------------
__global__ void add_ln_kernel(float* __restrict__ x,
                              const float* __restrict__ y, int nsplit,
                              const float* __restrict__ s,
                              const float* __restrict__ b,
                              __nv_bfloat16* __restrict__ xh,
                              __nv_bfloat16* __restrict__ xl) {
    int row = blockIdx.x, tid = threadIdx.x;
    __shared__ float sh[8];
    const float4 xv = ((const float4*)(x + (size_t)row * D_))[tid];
    float r0 = xv.x, r1 = xv.y, r2 = xv.z, r3 = xv.w;
    for (int z = 0; z < nsplit; z++) {
        const float4 yv = ((const float4*)(y + (size_t)z * TOK_ * D_ + (size_t)row * D_))[tid];
        r0 += yv.x; r1 += yv.y; r2 += yv.z; r3 += yv.w;
    }

    float sum = r0 + r1 + r2 + r3;
    int lane = tid & 31, wp = tid >> 5;
#pragma unroll
    for (int off = 16; off > 0; off >>= 1) sum += __shfl_xor_sync(0xffffffffu, sum, off);
    if (lane == 0) sh[wp] = sum;
    __syncthreads();
    float mean = (sh[0] + sh[1] + sh[2] + sh[3]) * (1.0f / 512.0f);

    float d0 = r0 - mean, d1 = r1 - mean, d2 = r2 - mean, d3 = r3 - mean;
    float sq = d0 * d0 + d1 * d1 + d2 * d2 + d3 * d3;
#pragma unroll
    for (int off = 16; off > 0; off >>= 1) sq += __shfl_xor_sync(0xffffffffu, sq, off);
    if (lane == 0) sh[4 + wp] = sq;
    __syncthreads();
    float var = (sh[4] + sh[5] + sh[6] + sh[7]) * (1.0f / 512.0f);
    float rstd = 1.0f / sqrtf(var + 1e-5f);

    const float4 sv = ((const float4*)s)[tid];
    const float4 bv = ((const float4*)b)[tid];
    float o0 = d0 * rstd * sv.x + bv.x;
    float o1 = d1 * rstd * sv.y + bv.y;
    float o2 = d2 * rstd * sv.z + bv.z;
    float o3 = d3 * rstd * sv.w + bv.w;
    ((float4*)(x + (size_t)row * D_))[tid] = make_float4(o0, o1, o2, o3);

    size_t base = (size_t)row * D_ + tid * 4;
    __nv_bfloat16 h0, h1, h2, h3, l0, l1, l2, l3;
    split_hl(o0, h0, l0); split_hl(o1, h1, l1);
    split_hl(o2, h2, l2); split_hl(o3, h3, l3);
    ((__nv_bfloat162*)(xh + base))[0] = __nv_bfloat162(h0, h1);
    ((__nv_bfloat162*)(xh + base))[1] = __nv_bfloat162(h2, h3);
    ((__nv_bfloat162*)(xl + base))[0] = __nv_bfloat162(l0, l1);
    ((__nv_bfloat162*)(xl + base))[1] = __nv_bfloat162(l2, l3);
}

// ---------------------------------------------------------------------------
// Joiner A materialization -> single fp16
// ---------------------------------------------------------------------------
__global__ void joiner_a_kernel(const float* __restrict__ enc,
                                const float* __restrict__ x,
                                __half* __restrict__ A) {
    int r = blockIdx.x;
    int n = r / (TI_ * TS_);
    int rem = r - n * (TI_ * TS_);
    int i = rem / TS_;
    int t = rem - i * TS_;
    const float4* er = (const float4*)(enc + (size_t)(i * 8 + n) * D_);
    const float4* xr = (const float4*)(x + (size_t)(t * 8 + n) * D_);
    int tid = threadIdx.x;
    float4 e = er[tid], xx = xr[tid];
    __half2 h0 = __half2(__float2half(tanhf(e.x + xx.x)), __float2half(tanhf(e.y + xx.y)));
    __half2 h1 = __half2(__float2half(tanhf(e.z + xx.z)), __float2half(tanhf(e.w + xx.w)));
    size_t base = (size_t)r * D_ + tid * 4;
    ((__half2*)(A + base))[0] = h0;
    ((__half2*)(A + base))[1] = h1;
}

// ---------------------------------------------------------------------------
// Joiner GEMM (tile 128x128, K=512, plain fp16)
// ---------------------------------------------------------------------------
#define JT_CHUNKS   8

__global__ void __launch_bounds__(256) joiner_tc_kernel(
    const __half* __restrict__ A,
    const __half* __restrict__ W,
    float* __restrict__ C) {
    extern __shared__ char smem[];
    const uint32_t sbase = smem_to_u32(smem);
    const int tid = threadIdx.x;
    const int n0 = blockIdx.x * 128;
    const int m0 = blockIdx.y * 128;

#if USE_TCGEN05
    const int wid = tid >> 5, lane = tid & 31;

    if (wid == 0) {
        TCGEN05_ALLOC(sbase, 128);
        TCGEN05_RELINQUISH_ALLOC_PERMIT();
    }
    if (tid == 0) {
        MBARRIER_INIT(sbase + 8, 1);
        MBARRIER_INIT(sbase + 16, 1);
    }
    __syncthreads();
    uint32_t tmem_base;
    asm volatile("ld.shared.b32 %0, [%1];" : "=r"(tmem_base) : "r"(sbase));

    tc_load_tile_async((const __nv_bfloat16*)A, m0, MJ_, 0, D_, sbase + JJ_SM_A(0), tid);
    tc_load_tile_async((const __nv_bfloat16*)W, n0, VP_, 0, D_, sbase + JJ_SM_W(0), tid);
    cp_async_commit();

    for (int c = 0; c < JT_CHUNKS; c++) {
        const int st = c & 1;
        if (c + 1 < JT_CHUNKS) {
            const int st1 = (c + 1) & 1;
            const int use = (c + 1) >> 1;
            if (use >= 1) {
                MBARRIER_WAIT_PARITY(sbase + 8 + 8 * st1, (use - 1) & 1);
            }
            tc_load_tile_async((const __nv_bfloat16*)A, m0, MJ_, (c + 1) * 64, D_,
                               sbase + JJ_SM_A(st1), tid);
            tc_load_tile_async((const __nv_bfloat16*)W, n0, VP_, (c + 1) * 64, D_,
                               sbase + JJ_SM_W(st1), tid);
            cp_async_commit();
            cp_async_wait<1>();
        } else {
            cp_async_wait<0>();
        }
        __syncthreads();
        if (wid == 0) {
            if (elect_one_pred()) {
                FENCE_PROXY_ASYNC_SHARED_CTA();
                const uint64_t dA = MAKE_SMEM_DESC(sbase + JJ_SM_A(st));
                const uint64_t dW = MAKE_SMEM_DESC(sbase + JJ_SM_W(st));
#pragma unroll
                for (int k = 0; k < 4; k++)
                    mma_f16_ss_cg1(tmem_base, dA + k * 2, dW + k * 2,
                                   JOINER_IDESC_F16, (c > 0) || (k > 0));
                TCGEN05_COMMIT(sbase + 8 + 8 * st);
            }
        }
        __syncthreads();
    }
    MBARRIER_WAIT_PARITY(sbase + 8, 1);
    MBARRIER_WAIT_PARITY(sbase + 16, 1);
    TCGEN05_FENCE_AFTER();

    {
        const int sub = wid & 3;
        const int halfc = (wid >> 2) * 64;
        float* crow = C + (size_t)(m0 + sub * 32 + lane) * V_;
        const bool full = (n0 + 128) <= V_;
#pragma unroll
        for (int base = halfc; base < halfc + 64; base += 32) {
            uint32_t r[32];
            TCGEN05_LD_32X32B_X32(r, tmem_base + base);
            TCGEN05_WAIT_LD();
            if (full) {
#pragma unroll
                for (int j = 0; j < 32; j += 4) {
                    stg_cs_f4(crow + n0 + base + j,
                              __uint_as_float(r[j]), __uint_as_float(r[j + 1]),
                              __uint_as_float(r[j + 2]), __uint_as_float(r[j + 3]));
                }
            } else {
#pragma unroll
                for (int j = 0; j < 32; j++) {
                    int col = n0 + base + j;
                    if (col < V_) stg_cs_f1(crow + col, __uint_as_float(r[j]));
                }
            }
        }
    }
    __syncthreads();
    if (tid == 0) {
        MBARRIER_INVAL(sbase + 8);
        MBARRIER_INVAL(sbase + 16);
    }
    __syncthreads();
    if (wid == 0) {
        TCGEN05_DEALLOC(tmem_base, 128);
    }

#else  // mma.sync path (the one that actually runs on base sm_103)
    const int w = tid >> 5, lane = tid & 31;
    const int wr = w >> 1, wc = w & 1;

    float acc[16][4];
#pragma unroll
    for (int i = 0; i < 16; i++)
#pragma unroll
        for (int j = 0; j < 4; j++) acc[i][j] = 0.f;

    const int nhalf = JT_CHUNKS * 2;
    load_half2_j(A, W, m0, n0, 0, sbase, tid, 0);
    cp_async_commit();
    for (int c = 0; c < nhalf; c++) {
        if (c + 1 < nhalf) {
            load_half2_j(A, W, m0, n0, (c + 1) * 32, sbase, tid, (c + 1) & 1);
            cp_async_commit();
            cp_async_wait<1>();
        } else {
            cp_async_wait<0>();
        }
        __syncthreads();
        mma_mainloop_half_j(sbase, wr, wc, lane, acc, c & 1);
        __syncthreads();
    }

#pragma unroll
    for (int mi = 0; mi < 2; mi++) {
#pragma unroll
        for (int nt = 0; nt < 8; nt++) {
            int m = m0 + wr * 32 + mi * 16 + (lane >> 2);
            int ncol = n0 + wc * 64 + nt * 8 + 2 * (lane & 3);
            if (ncol < V_) {
                stg_cs_f2(C + (size_t)m * V_ + ncol,
                          acc[mi * 8 + nt][0], acc[mi * 8 + nt][1]);
                stg_cs_f2(C + (size_t)(m + 8) * V_ + ncol,
                          acc[mi * 8 + nt][2], acc[mi * 8 + nt][3]);
            }
        }
    }
#endif
}

// ---------------------------------------------------------------------------
// Host orchestration
// ---------------------------------------------------------------------------
extern "C" void kernel_launch(void* const* d_in, const int* in_sizes, int n_in,
                              void* d_out, int out_size) {
    const float* enc_out = (const float*)d_in[0];
    const float* embed_w = (const float*)d_in[1];
    const float* enc_w   = (const float*)d_in[2];
    const float* enc_b   = (const float*)d_in[3];
    const float* qkv_w   = (const float*)d_in[4];
    const float* qkv_b   = (const float*)d_in[5];
    const float* o_w     = (const float*)d_in[6];
    const float* o_b     = (const float*)d_in[7];
    const float* ln1_s   = (const float*)d_in[8];
    const float* ln1_b   = (const float*)d_in[9];
    const float* ff1_w   = (const float*)d_in[10];
    const float* ff1_b   = (const float*)d_in[11];
    const float* ff2_w   = (const float*)d_in[12];
    const float* ff2_b   = (const float*)d_in[13];
    const float* ln2_s   = (const float*)d_in[14];
    const float* ln2_b   = (const float*)d_in[15];
    const float* out_w   = (const float*)d_in[16];
    const int*   tgt_pad = (const int*)d_in[17];
    const int*   tgt_len = (const int*)d_in[18];
    const int*   sos     = (const int*)d_in[19];

    float *x, *qkv, *tmp, *encp;
    cudaGetSymbolAddress((void**)&x, g_x);
    cudaGetSymbolAddress((void**)&qkv, g_qkv);
    cudaGetSymbolAddress((void**)&tmp, g_tmp);
    cudaGetSymbolAddress((void**)&encp, g_encp);

    __nv_bfloat16 *xh, *xl, *ath, *atl, *fh, *fl;
    cudaGetSymbolAddress((void**)&xh, g_xh);
    cudaGetSymbolAddress((void**)&xl, g_xl);
    cudaGetSymbolAddress((void**)&ath, g_ath);
    cudaGetSymbolAddress((void**)&atl, g_atl);
    cudaGetSymbolAddress((void**)&fh, g_fh);
    cudaGetSymbolAddress((void**)&fl, g_fl);

    __nv_bfloat16 *qkvwh, *qkvwl, *owh, *owl, *f1h, *f1l, *f2h, *f2l, *ewh, *ewl, *exh, *exl;
    cudaGetSymbolAddress((void**)&qkvwh, g_qkvwh);
    cudaGetSymbolAddress((void**)&qkvwl, g_qkvwl);
    cudaGetSymbolAddress((void**)&owh, g_owh);
    cudaGetSymbolAddress((void**)&owl, g_owl);
    cudaGetSymbolAddress((void**)&f1h, g_f1h);
    cudaGetSymbolAddress((void**)&f1l, g_f1l);
    cudaGetSymbolAddress((void**)&f2h, g_f2h);
    cudaGetSymbolAddress((void**)&f2l, g_f2l);
    cudaGetSymbolAddress((void**)&ewh, g_ewh);
    cudaGetSymbolAddress((void**)&ewl, g_ewl);
    cudaGetSymbolAddress((void**)&exh, g_exh);
    cudaGetSymbolAddress((void**)&exl, g_exl);

    __half *Aj, *Wj;
    cudaGetSymbolAddress((void**)&Aj, g_Aj);
    cudaGetSymbolAddress((void**)&Wj, g_Wj);

    static bool attr_done = false;
    if (!attr_done) {
        cudaFuncSetAttribute(joiner_tc_kernel,
                             cudaFuncAttributeMaxDynamicSharedMemorySize, JJ_SMEM_LAUNCH);
        cudaFuncSetAttribute(gemm_tc,
                             cudaFuncAttributeMaxDynamicSharedMemorySize, JT_SMEM);
        attr_done = true;
    }

    // ---- fused weight splits + padded fp16 out_w ----
    {
        SplitJobs jobs;
        int c0 = L_ * 3 * D_ * D_ / 4;
        int c1 = L_ * D_ * D_ / 4;
        int c2 = L_ * FF_ * D_ / 4;
        int c3 = L_ * D_ * FF_ / 4;
        int c4 = D_ * D_ / 4;
        int c5 = TI_ * NB_ * D_ / 4;
        jobs.src[0] = qkv_w;  jobs.h[0] = qkvwh; jobs.l[0] = qkvwl; jobs.end[0] = c0;
        jobs.src[1] = o_w;    jobs.h[1] = owh;   jobs.l[1] = owl;   jobs.end[1] = jobs.end[0] + c1;
        jobs.src[2] = ff1_w;  jobs.h[2] = f1h;   jobs.l[2] = f1l;   jobs.end[2] = jobs.end[1] + c2;
        jobs.src[3] = ff2_w;  jobs.h[3] = f2h;   jobs.l[3] = f2l;   jobs.end[3] = jobs.end[2] + c3;
        jobs.src[4] = enc_w;  jobs.h[4] = ewh;   jobs.l[4] = ewl;   jobs.end[4] = jobs.end[3] + c4;
        jobs.src[5] = enc_out;jobs.h[5] = exh;   jobs.l[5] = exl;   jobs.end[5] = jobs.end[4] + c5;
        int total = jobs.end[5];
        split_all_kernel<<<(total + 255) / 256, 256>>>(jobs, total);
        w_split_kernel<<<VP_, 128>>>(out_w, Wj);
    }

    // enc projection
    gemm_tc<<<dim3(D_ / 128, (TI_ * NB_) / 128, 1), 256, JT_SMEM>>>(
        exh, exl, ewh, ewl, enc_b, encp, nullptr, nullptr,
        TI_ * NB_, D_, D_, 8, 0);

    // embedding + positions
    embed_kernel<<<TOK_, 128>>>(embed_w, tgt_pad, sos, x, xh, xl);

    // 6 post-norm transformer layers
    for (int l = 0; l < L_; l++) {
        gemm_tc<<<dim3(3 * D_ / 128, 3, QKV_SPLIT), 256, JT_SMEM>>>(
            xh, xl, qkvwh + (size_t)l * 3 * D_ * D_, qkvwl + (size_t)l * 3 * D_ * D_,
            qkv_b + (size_t)l * 3 * D_, qkv, nullptr, nullptr,
            TOK_, 3 * D_, D_, 8 / QKV_SPLIT, 0);
        attention_kernel<<<NB_ * H_, 256>>>(qkv, tgt_len, ath, atl);
        gemm_tc<<<dim3(D_ / 128, 3, O_SPLIT), 256, JT_SMEM>>>(
            ath, atl, owh + (size_t)l * D_ * D_, owl + (size_t)l * D_ * D_,
            o_b + (size_t)l * D_, tmp, nullptr, nullptr,
            TOK_, D_, D_, 8 / O_SPLIT, 0);
        add_ln_kernel<<<TOK_, 128>>>(x, tmp, O_SPLIT,
            ln1_s + (size_t)l * D_, ln1_b + (size_t)l * D_, xh, xl);
        gemm_tc<<<dim3(FF_ / 128, 3, 1), 256, JT_SMEM>>>(
            xh, xl, f1h + (size_t)l * FF_ * D_, f1l + (size_t)l * FF_ * D_,
            ff1_b + (size_t)l * FF_, nullptr, fh, fl,
            TOK_, FF_, D_, 8, 1);
        gemm_tc<<<dim3(D_ / 128, 3, FF2_SPLIT), 256, JT_SMEM>>>(
            fh, fl, f2h + (size_t)l * D_ * FF_, f2l + (size_t)l * D_ * FF_,
            ff2_b + (size_t)l * D_, tmp, nullptr, nullptr,
            TOK_, D_, FF_, FF_ / 64 / FF2_SPLIT, 0);
        add_ln_kernel<<<TOK_, 128>>>(x, tmp, FF2_SPLIT,
            ln2_s + (size_t)l * D_, ln2_b + (size_t)l * D_, xh, xl);
    }

    // joiner
    joiner_a_kernel<<<MJ_, 128>>>(encp, x, Aj);
    joiner_tc_kernel<<<dim3(VP_ / 128, MJ_ / 128), 256, JJ_SMEM_LAUNCH>>>(
        Aj, Wj, (float*)d_out);
}